// round 6
// baseline (speedup 1.0000x reference)
#include <cuda_runtime.h>
#include <cuda_bf16.h>
#include <math.h>

#define B_  2
#define S_  2048
#define H_  2048
#define NH_ 16
#define HD_ 128
#define M_  (B_*S_)   // 4096 rows

// -------- scratch (device globals; no allocations allowed) --------
__device__ float g_h[(size_t)M_*H_];
__device__ float g_q[(size_t)M_*H_];
__device__ float g_k[(size_t)M_*H_];
__device__ float g_v[(size_t)M_*H_];
__device__ float g_ctx[(size_t)M_*H_];

// ===================== naive RMSNorm =====================
// var = mean(x^2) over the row; h = w * x * rsqrt(var + eps)
__global__ void rmsnorm_naive(const float* __restrict__ x, const float* __restrict__ w) {
    int row = blockIdx.x;
    __shared__ float red[256];
    float ss = 0.f;
    for (int i = threadIdx.x; i < H_; i += 256) {
        float v = x[(size_t)row * H_ + i];
        ss += v * v;
    }
    red[threadIdx.x] = ss;
    __syncthreads();
    for (int s = 128; s; s >>= 1) {
        if (threadIdx.x < s) red[threadIdx.x] += red[threadIdx.x + s];
        __syncthreads();
    }
    float inv = rsqrtf(red[0] * (1.0f / (float)H_) + 1e-6f);
    for (int i = threadIdx.x; i < H_; i += 256)
        g_h[(size_t)row * H_ + i] = w[i] * (x[(size_t)row * H_ + i] * inv);
}

// ===================== naive GEMM =====================
// C[m][n] = sum_k A[m][k] * W[n][k]   (y = h @ W.T, W row-major [out,in])
// a_sel: 0 -> g_h, 1 -> g_ctx.  c_sel: 0 g_q, 1 g_k, 2 g_v, 3 extC.
__global__ void gemm_naive(int a_sel, const float* __restrict__ W, int c_sel,
                           float* __restrict__ extC) {
    const float* A = a_sel ? g_ctx : g_h;
    float* C = (c_sel == 0) ? g_q : (c_sel == 1) ? g_k : (c_sel == 2) ? g_v : extC;
    int m = blockIdx.x;
    int n = blockIdx.y * 256 + threadIdx.x;
    const float* a = A + (size_t)m * H_;
    const float* w = W + (size_t)n * H_;
    float acc = 0.f;
    for (int k = 0; k < H_; k++) acc += a[k] * w[k];
    C[(size_t)m * H_ + n] = acc;
}

// ===================== naive RoPE =====================
// q' [j]    = q[j]*cos(ang_j) - q[j+64]*sin(ang_j)
// q' [j+64] = q[j+64]*cos(ang_j) + q[j]*sin(ang_j),  ang_j = pos * base^(-2j/128)
__global__ void rope_naive(const int* __restrict__ pos_ids) {
    int row = blockIdx.x;            // b*S + s
    int b = row / S_;
    int s = row - b * S_;
    int pos = pos_ids[b * S_ + s];
    for (int u = threadIdx.x; u < NH_ * 64; u += 256) {
        int hh = u >> 6, j = u & 63;
        float invf = (float)exp(-(double)(2 * j) * (1.0 / 128.0) * log(10000.0));
        float ang = (float)pos * invf;
        float c = cosf(ang), sn = sinf(ang);
        size_t base = (size_t)row * H_ + hh * HD_;
        float q1 = g_q[base + j], q2 = g_q[base + j + 64];
        g_q[base + j]      = q1 * c - q2 * sn;
        g_q[base + j + 64] = q2 * c + q1 * sn;
        float k1 = g_k[base + j], k2 = g_k[base + j + 64];
        g_k[base + j]      = k1 * c - k2 * sn;
        g_k[base + j + 64] = k2 * c + k1 * sn;
    }
}

// ===================== naive attention =====================
// One block (128 threads) per (query position, batch-head).
// Materialize the full causal score row, exact softmax, then PV.
__global__ void attn_naive() {
    int q  = blockIdx.x;             // 0..S-1
    int bh = blockIdx.y;             // 0..B*NH-1
    int b = bh / NH_, hh = bh % NH_;
    int tid = threadIdx.x;           // 128 threads

    __shared__ float qv[HD_];
    __shared__ float sc[S_];
    __shared__ float red[128];

    const float scale = 0.08838834764831845f;   // 1/sqrt(128)
    qv[tid] = g_q[(size_t)(b * S_ + q) * H_ + hh * HD_ + tid];
    __syncthreads();

    // scores for keys 0..q (masked keys' exp(score-10000-max) underflows to 0 exactly)
    for (int j = tid; j <= q; j += 128) {
        const float* Kr = g_k + (size_t)(b * S_ + j) * H_ + hh * HD_;
        float d = 0.f;
        for (int dd = 0; dd < HD_; dd++) d += qv[dd] * Kr[dd];
        sc[j] = d * scale;
    }
    __syncthreads();

    // row max
    float mx = -1e30f;
    for (int j = tid; j <= q; j += 128) mx = fmaxf(mx, sc[j]);
    red[tid] = mx;
    __syncthreads();
    for (int s = 64; s; s >>= 1) {
        if (tid < s) red[tid] = fmaxf(red[tid], red[tid + s]);
        __syncthreads();
    }
    mx = red[0];
    __syncthreads();

    // exp and sum
    float sum = 0.f;
    for (int j = tid; j <= q; j += 128) {
        float p = expf(sc[j] - mx);
        sc[j] = p;
        sum += p;
    }
    red[tid] = sum;
    __syncthreads();
    for (int s = 64; s; s >>= 1) {
        if (tid < s) red[tid] += red[tid + s];
        __syncthreads();
    }
    float inv = 1.0f / red[0];
    __syncthreads();

    // PV: thread owns output dim `tid`
    float acc = 0.f;
    for (int j = 0; j <= q; j++)
        acc += sc[j] * g_v[(size_t)(b * S_ + j) * H_ + hh * HD_ + tid];
    g_ctx[(size_t)(b * S_ + q) * H_ + hh * HD_ + tid] = acc * inv;
}

// ===================== launch =====================
extern "C" void kernel_launch(void* const* d_in, const int* in_sizes, int n_in,
                              void* d_out, int out_size) {
    (void)out_size;
    // Runtime slot detection from unique sizes:
    //   x = 8388608, norm_w = 2048, pos = 4096, weights = 4194304 (keep order q,k,v,o)
    const float* x  = nullptr;
    const float* nw = nullptr;
    const int*  pos = nullptr;
    const float* wts[4] = {nullptr, nullptr, nullptr, nullptr};
    int wn = 0;
    for (int i = 0; i < n_in; i++) {
        int sz = in_sizes[i];
        if (sz == B_ * S_ * H_)      x = (const float*)d_in[i];
        else if (sz == H_)           nw = (const float*)d_in[i];
        else if (sz == B_ * S_)      pos = (const int*)d_in[i];
        else if (sz == H_ * H_ && wn < 4) wts[wn++] = (const float*)d_in[i];
    }
    const float* wq = wts[0];
    const float* wk = wts[1];
    const float* wv = wts[2];
    const float* wo = wts[3];
    float* out = (float*)d_out;

    rmsnorm_naive<<<M_, 256>>>(x, nw);

    dim3 gg(M_, H_ / 256);
    gemm_naive<<<gg, 256>>>(0, wq, 0, nullptr);
    gemm_naive<<<gg, 256>>>(0, wk, 1, nullptr);
    gemm_naive<<<gg, 256>>>(0, wv, 2, nullptr);

    rope_naive<<<M_, 256>>>(pos);

    attn_naive<<<dim3(S_, B_ * NH_), 128>>>();

    gemm_naive<<<gg, 256>>>(1, wo, 3, out);
}

// round 7
// speedup vs baseline: 52.8905x; 52.8905x over previous
#include <cuda_runtime.h>
#include <cuda_bf16.h>
#include <math.h>

#define B_  2
#define S_  2048
#define H_  2048
#define NH_ 16
#define HD_ 128
#define M_  (B_*S_)   // 4096 rows

// -------- scratch (device globals; no allocations allowed) --------
__device__ float g_h[(size_t)M_*H_];
__device__ float g_q[(size_t)M_*H_];
__device__ float g_k[(size_t)M_*H_];
__device__ float g_v[(size_t)M_*H_];
__device__ float g_ctx[(size_t)M_*H_];

// ===================== RMSNorm (proven in R6) =====================
__global__ void rmsnorm_naive(const float* __restrict__ x, const float* __restrict__ w) {
    int row = blockIdx.x;
    __shared__ float red[256];
    float ss = 0.f;
    for (int i = threadIdx.x; i < H_; i += 256) {
        float v = x[(size_t)row * H_ + i];
        ss += v * v;
    }
    red[threadIdx.x] = ss;
    __syncthreads();
    for (int s = 128; s; s >>= 1) {
        if (threadIdx.x < s) red[threadIdx.x] += red[threadIdx.x + s];
        __syncthreads();
    }
    float inv = rsqrtf(red[0] * (1.0f / (float)H_) + 1e-6f);
    for (int i = threadIdx.x; i < H_; i += 256)
        g_h[(size_t)row * H_ + i] = w[i] * (x[(size_t)row * H_ + i] * inv);
}

// ===================== Tiled SGEMM (fresh rewrite) =====================
// C[m][n] = sum_k A[m][k] * W[n][k]
// a_sel: 0 -> g_h, 1 -> g_ctx.  c_sel: 0 g_q, 1 g_k, 2 g_v, 3 extC.
#define TM 128
#define TN 128
#define TK 16
#define LDP 132

__global__ void gemm_tiled(int a_sel, const float* __restrict__ W, int c_sel,
                           float* __restrict__ extC) {
    __shared__ float As[TK][LDP];
    __shared__ float Bs[TK][LDP];
    const float* A = a_sel ? g_ctx : g_h;
    float* C = (c_sel == 0) ? g_q : (c_sel == 1) ? g_k : (c_sel == 2) ? g_v : extC;

    const int t  = threadIdx.x;            // 0..255
    const int bm = blockIdx.y * TM;
    const int bn = blockIdx.x * TN;

    // loader mapping: thread -> (tile row lr, k-offset lk in {0,8}), 2 float4 each from A and W
    const int lr = t >> 1;                 // 0..127
    const int lk = (t & 1) << 3;           // 0 or 8
    const float* Ag = A + (size_t)(bm + lr) * H_ + lk;
    const float* Wg = W + (size_t)(bn + lr) * H_ + lk;

    // compute mapping: 8x8 microtile at (cy, cx)
    const int cx = (t & 15) << 3;          // 0..120
    const int cy = (t >> 4) << 3;          // 0..120

    float acc[8][8];
#pragma unroll
    for (int i = 0; i < 8; i++)
#pragma unroll
        for (int j = 0; j < 8; j++) acc[i][j] = 0.f;

    float4 ra0 = *(const float4*)(Ag + 0);
    float4 ra1 = *(const float4*)(Ag + 4);
    float4 rb0 = *(const float4*)(Wg + 0);
    float4 rb1 = *(const float4*)(Wg + 4);

    for (int kt = 0; kt < H_; kt += TK) {
        As[lk+0][lr] = ra0.x; As[lk+1][lr] = ra0.y; As[lk+2][lr] = ra0.z; As[lk+3][lr] = ra0.w;
        As[lk+4][lr] = ra1.x; As[lk+5][lr] = ra1.y; As[lk+6][lr] = ra1.z; As[lk+7][lr] = ra1.w;
        Bs[lk+0][lr] = rb0.x; Bs[lk+1][lr] = rb0.y; Bs[lk+2][lr] = rb0.z; Bs[lk+3][lr] = rb0.w;
        Bs[lk+4][lr] = rb1.x; Bs[lk+5][lr] = rb1.y; Bs[lk+6][lr] = rb1.z; Bs[lk+7][lr] = rb1.w;
        __syncthreads();

        if (kt + TK < H_) {
            ra0 = *(const float4*)(Ag + kt + TK);
            ra1 = *(const float4*)(Ag + kt + TK + 4);
            rb0 = *(const float4*)(Wg + kt + TK);
            rb1 = *(const float4*)(Wg + kt + TK + 4);
        }

#pragma unroll
        for (int k = 0; k < TK; k++) {
            float av[8], bv[8];
            *(float4*)(av)   = *(const float4*)&As[k][cy];
            *(float4*)(av+4) = *(const float4*)&As[k][cy+4];
            *(float4*)(bv)   = *(const float4*)&Bs[k][cx];
            *(float4*)(bv+4) = *(const float4*)&Bs[k][cx+4];
#pragma unroll
            for (int i = 0; i < 8; i++)
#pragma unroll
                for (int j = 0; j < 8; j++)
                    acc[i][j] = fmaf(av[i], bv[j], acc[i][j]);
        }
        __syncthreads();
    }

#pragma unroll
    for (int i = 0; i < 8; i++) {
        float* cp = C + (size_t)(bm + cy + i) * H_ + bn + cx;
        *(float4*)(cp)     = make_float4(acc[i][0], acc[i][1], acc[i][2], acc[i][3]);
        *(float4*)(cp + 4) = make_float4(acc[i][4], acc[i][5], acc[i][6], acc[i][7]);
    }
}

// ===================== RoPE (proven in R6) =====================
__global__ void rope_naive(const int* __restrict__ pos_ids) {
    int row = blockIdx.x;            // b*S + s
    int b = row / S_;
    int s = row - b * S_;
    int pos = pos_ids[b * S_ + s];
    for (int u = threadIdx.x; u < NH_ * 64; u += 256) {
        int hh = u >> 6, j = u & 63;
        float invf = (float)exp(-(double)(2 * j) * (1.0 / 128.0) * log(10000.0));
        float ang = (float)pos * invf;
        float c = cosf(ang), sn = sinf(ang);
        size_t base = (size_t)row * H_ + hh * HD_;
        float q1 = g_q[base + j], q2 = g_q[base + j + 64];
        g_q[base + j]      = q1 * c - q2 * sn;
        g_q[base + j + 64] = q2 * c + q1 * sn;
        float k1 = g_k[base + j], k2 = g_k[base + j + 64];
        g_k[base + j]      = k1 * c - k2 * sn;
        g_k[base + j + 64] = k2 * c + k1 * sn;
    }
}

// ===================== Flash attention (fresh rewrite) =====================
// grid (S/64, B*NH), 256 threads. 64x64 tiles, D=128.
// K stored UNtransposed with 129-float row pitch (stride == 1 mod 32 ->
// per-lane column dot-products are bank-conflict-free).
// Phase 2: thread r (r<64) owns the online softmax for query row r.
#define ASM_FLOATS 29568
// Qs [64][132] @0, Ks [64][129] @8448, Vs [64][132] @16704,
// Ps [64][66] @25152, rm @29376, rl @29440, rc @29504

__global__ void attn_fast() {
    extern __shared__ float sm[];
    float* Qs = sm;
    float* Ks = sm + 8448;
    float* Vs = sm + 16704;
    float* Ps = sm + 25152;
    float* rm = sm + 29376;
    float* rl = sm + 29440;
    float* rc = sm + 29504;

    int qi = blockIdx.x, bh = blockIdx.y;
    int b = bh / NH_, hh = bh % NH_;
    int t = threadIdx.x, lane = t & 31, w = t >> 5;
    int r0 = w << 3;

    const float* Qg = g_q + (size_t)(b * S_) * H_ + hh * HD_;
    const float* Kg = g_k + (size_t)(b * S_) * H_ + hh * HD_;
    const float* Vg = g_v + (size_t)(b * S_) * H_ + hh * HD_;

    for (int i = t; i < 64 * 32; i += 256) {
        int r = i >> 5, d4 = (i & 31) << 2;
        *(float4*)&Qs[r * 132 + d4] = *(const float4*)(Qg + (size_t)(qi * 64 + r) * H_ + d4);
    }
    if (t < 64) { rm[t] = -1e30f; rl[t] = 0.f; }

    float acc[8][4];
#pragma unroll
    for (int i = 0; i < 8; i++) { acc[i][0] = acc[i][1] = acc[i][2] = acc[i][3] = 0.f; }

    const float scale = 0.08838834764831845f;   // 1/sqrt(128)

    for (int kt = 0; kt <= qi; kt++) {
        __syncthreads();   // prior phase-3 reads done; first iter: Qs/rm/rl ready
        for (int i = t; i < 64 * 32; i += 256) {
            int r = i >> 5, d4 = (i & 31) << 2;
            float4 kv = *(const float4*)(Kg + (size_t)(kt * 64 + r) * H_ + d4);
            Ks[r * 129 + d4 + 0] = kv.x;
            Ks[r * 129 + d4 + 1] = kv.y;
            Ks[r * 129 + d4 + 2] = kv.z;
            Ks[r * 129 + d4 + 3] = kv.w;
            *(float4*)&Vs[r * 132 + d4] = *(const float4*)(Vg + (size_t)(kt * 64 + r) * H_ + d4);
        }
        __syncthreads();

        // ---- phase 1: scores. warp w -> rows r0..r0+7, lane -> cols {lane, lane+32}
        float s0[8], s1[8];
#pragma unroll
        for (int i = 0; i < 8; i++) { s0[i] = 0.f; s1[i] = 0.f; }
        const float* Ka = &Ks[lane * 129];
        const float* Kb2 = &Ks[(lane + 32) * 129];
#pragma unroll 4
        for (int d4 = 0; d4 < 128; d4 += 4) {
            float ka0 = Ka[d4+0], ka1 = Ka[d4+1], ka2 = Ka[d4+2], ka3 = Ka[d4+3];
            float kb0 = Kb2[d4+0], kb1 = Kb2[d4+1], kb2 = Kb2[d4+2], kb3 = Kb2[d4+3];
#pragma unroll
            for (int i = 0; i < 8; i++) {
                float4 qv = *(const float4*)&Qs[(r0 + i) * 132 + d4];
                s0[i] += qv.x * ka0 + qv.y * ka1 + qv.z * ka2 + qv.w * ka3;
                s1[i] += qv.x * kb0 + qv.y * kb1 + qv.z * kb2 + qv.w * kb3;
            }
        }
#pragma unroll
        for (int i = 0; i < 8; i++) {
            Ps[(r0 + i) * 66 + lane]      = s0[i];
            Ps[(r0 + i) * 66 + lane + 32] = s1[i];
        }
        __syncthreads();

        // ---- phase 2: per-row online softmax
        if (t < 64) {
            int r = t, grow = qi * 64 + r, cb = kt * 64;
            float mold = rm[r];
            float tmax = mold;
#pragma unroll 8
            for (int c = 0; c < 64; c++) {
                float a = Ps[r * 66 + c] * scale;
                if (cb + c > grow) a -= 10000.0f;
                Ps[r * 66 + c] = a;
                tmax = fmaxf(tmax, a);
            }
            float corr = __expf(mold - tmax);
            float psum = 0.f;
#pragma unroll 8
            for (int c = 0; c < 64; c++) {
                float p = __expf(Ps[r * 66 + c] - tmax);
                Ps[r * 66 + c] = p;
                psum += p;
            }
            rl[r] = rl[r] * corr + psum;
            rm[r] = tmax;
            rc[r] = corr;
        }
        __syncthreads();

        // ---- phase 3: PV accumulate. lane owns dims d4..d4+3
        int d4 = lane << 2;
#pragma unroll
        for (int i = 0; i < 8; i++) {
            float corr = rc[r0 + i];
            acc[i][0] *= corr; acc[i][1] *= corr; acc[i][2] *= corr; acc[i][3] *= corr;
        }
#pragma unroll 2
        for (int c = 0; c < 64; c++) {
            float4 vv = *(const float4*)&Vs[c * 132 + d4];
#pragma unroll
            for (int i = 0; i < 8; i++) {
                float p = Ps[(r0 + i) * 66 + c];
                acc[i][0] += p * vv.x; acc[i][1] += p * vv.y;
                acc[i][2] += p * vv.z; acc[i][3] += p * vv.w;
            }
        }
    }

    int d4 = lane << 2;
#pragma unroll
    for (int i = 0; i < 8; i++) {
        float invl = 1.0f / rl[r0 + i];
        float* op = g_ctx + (size_t)(b * S_ + qi * 64 + r0 + i) * H_ + hh * HD_ + d4;
        *(float4*)op = make_float4(acc[i][0] * invl, acc[i][1] * invl,
                                   acc[i][2] * invl, acc[i][3] * invl);
    }
}

// ===================== launch =====================
extern "C" void kernel_launch(void* const* d_in, const int* in_sizes, int n_in,
                              void* d_out, int out_size) {
    (void)out_size;
    // Runtime slot detection (proven in R6):
    //   x = 8388608, norm_w = 2048, pos = 4096, weights = 4194304 (keep order q,k,v,o)
    const float* x  = nullptr;
    const float* nw = nullptr;
    const int*  pos = nullptr;
    const float* wts[4] = {nullptr, nullptr, nullptr, nullptr};
    int wn = 0;
    for (int i = 0; i < n_in; i++) {
        int sz = in_sizes[i];
        if (sz == B_ * S_ * H_)      x = (const float*)d_in[i];
        else if (sz == H_)           nw = (const float*)d_in[i];
        else if (sz == B_ * S_)      pos = (const int*)d_in[i];
        else if (sz == H_ * H_ && wn < 4) wts[wn++] = (const float*)d_in[i];
    }
    const float* wq = wts[0];
    const float* wk = wts[1];
    const float* wv = wts[2];
    const float* wo = wts[3];
    float* out = (float*)d_out;

    rmsnorm_naive<<<M_, 256>>>(x, nw);

    dim3 gg(H_ / TN, M_ / TM);
    gemm_tiled<<<gg, 256>>>(0, wq, 0, nullptr);
    gemm_tiled<<<gg, 256>>>(0, wk, 1, nullptr);
    gemm_tiled<<<gg, 256>>>(0, wv, 2, nullptr);

    rope_naive<<<M_, 256>>>(pos);

    cudaFuncSetAttribute(attn_fast, cudaFuncAttributeMaxDynamicSharedMemorySize,
                         ASM_FLOATS * 4);
    attn_fast<<<dim3(S_ / 64, B_ * NH_), 256, ASM_FLOATS * 4>>>();

    gemm_tiled<<<gg, 256>>>(1, wo, 3, out);
}

// round 10
// speedup vs baseline: 88.5240x; 1.6737x over previous
#include <cuda_runtime.h>
#include <cuda_bf16.h>
#include <math.h>
#include <stdint.h>

#define B_  2
#define S_  2048
#define H_  2048
#define NH_ 16
#define HD_ 128
#define M_  (B_*S_)   // 4096 rows

// -------- scratch (device globals; no allocations allowed) --------
__device__ float g_h[(size_t)M_*H_];
__device__ float g_q[(size_t)M_*H_];
__device__ float g_k[(size_t)M_*H_];
__device__ float g_v[(size_t)M_*H_];
__device__ float g_ctx[(size_t)M_*H_];
// bf16 hi/lo splits: A-side (g_h or g_ctx) and the 4 weights
__device__ __nv_bfloat16 g_ah[(size_t)M_*H_];
__device__ __nv_bfloat16 g_al[(size_t)M_*H_];
__device__ __nv_bfloat16 g_wh[(size_t)4*H_*H_];
__device__ __nv_bfloat16 g_wl[(size_t)4*H_*H_];

__device__ __forceinline__ uint32_t smem_u32(const void* p) {
    uint32_t a;
    asm("{ .reg .u64 t; cvta.to.shared.u64 t, %1; cvt.u32.u64 %0, t; }" : "=r"(a) : "l"(p));
    return a;
}

// ===================== RMSNorm (proven) =====================
__global__ void rmsnorm_naive(const float* __restrict__ x, const float* __restrict__ w) {
    int row = blockIdx.x;
    __shared__ float red[256];
    float ss = 0.f;
    for (int i = threadIdx.x; i < H_; i += 256) {
        float v = x[(size_t)row * H_ + i];
        ss += v * v;
    }
    red[threadIdx.x] = ss;
    __syncthreads();
    for (int s = 128; s; s >>= 1) {
        if (threadIdx.x < s) red[threadIdx.x] += red[threadIdx.x + s];
        __syncthreads();
    }
    float inv = rsqrtf(red[0] * (1.0f / (float)H_) + 1e-6f);
    for (int i = threadIdx.x; i < H_; i += 256)
        g_h[(size_t)row * H_ + i] = w[i] * (x[(size_t)row * H_ + i] * inv);
}

// ===================== fp32 -> bf16 hi/lo split =====================
__global__ void conv_split(int src_sel, const float* __restrict__ ext,
                           int dst_sel, size_t dst_off) {
    const float* src = (src_sel == 0) ? g_h : (src_sel == 1) ? g_ctx : ext;
    __nv_bfloat16* dh = (dst_sel == 0) ? g_ah : (g_wh + dst_off);
    __nv_bfloat16* dl = (dst_sel == 0) ? g_al : (g_wl + dst_off);
    size_t i = (size_t)blockIdx.x * 256 + threadIdx.x;   // quad index
    float4 v = ((const float4*)src)[i];
    __nv_bfloat16 h0 = __float2bfloat16(v.x);
    __nv_bfloat16 h1 = __float2bfloat16(v.y);
    __nv_bfloat16 h2 = __float2bfloat16(v.z);
    __nv_bfloat16 h3 = __float2bfloat16(v.w);
    __nv_bfloat16 l0 = __float2bfloat16(v.x - __bfloat162float(h0));
    __nv_bfloat16 l1 = __float2bfloat16(v.y - __bfloat162float(h1));
    __nv_bfloat16 l2 = __float2bfloat16(v.z - __bfloat162float(h2));
    __nv_bfloat16 l3 = __float2bfloat16(v.w - __bfloat162float(h3));
    ((__nv_bfloat162*)dh)[2*i]   = __nv_bfloat162(h0, h1);
    ((__nv_bfloat162*)dh)[2*i+1] = __nv_bfloat162(h2, h3);
    ((__nv_bfloat162*)dl)[2*i]   = __nv_bfloat162(l0, l1);
    ((__nv_bfloat162*)dl)[2*i+1] = __nv_bfloat162(l2, l3);
}

// ===================== mma.sync bf16x3 GEMM =====================
// C[m][n] = sum_k A[m][k]*W[n][k]; CTA 128x128, 8 warps (warp tile 64x32),
// KC=32 double-buffered via cp.async. Row pitch 40 bf16 (conflict-free frags).
#define KC    32
#define RS    40                    // bf16 row pitch in smem
#define TILEB (128*RS*2)            // 10240 bytes per operand tile
#define STAGEB (4*TILEB)            // 40960 per stage
#define GSM_TOTAL (2*STAGEB)        // 81920

__device__ __forceinline__ void mma_bf16(float& c0, float& c1, float& c2, float& c3,
                                         uint32_t a0, uint32_t a1, uint32_t a2, uint32_t a3,
                                         uint32_t b0, uint32_t b1) {
    asm volatile(
        "mma.sync.aligned.m16n8k16.row.col.f32.bf16.bf16.f32 "
        "{%0,%1,%2,%3}, {%4,%5,%6,%7}, {%8,%9}, {%0,%1,%2,%3};"
        : "+f"(c0), "+f"(c1), "+f"(c2), "+f"(c3)
        : "r"(a0), "r"(a1), "r"(a2), "r"(a3), "r"(b0), "r"(b1));
}
#define CP16(dst, src) \
    asm volatile("cp.async.cg.shared.global [%0], [%1], 16;" :: "r"(dst), "l"(src))

__global__ void __launch_bounds__(256) gemm_mma(int w_idx, int c_sel, float* __restrict__ extC) {
    extern __shared__ char smem[];
    const uint32_t sb = smem_u32(smem);
    const int t = threadIdx.x, lane = t & 31, warp = t >> 5;
    const int wm = warp & 1, wn = warp >> 1;       // warp tile origin (wm*64, wn*32)
    const int g = lane >> 2, tig2 = (lane & 3) * 2;
    const int bm = blockIdx.y * 128, bn = blockIdx.x * 128;

    const __nv_bfloat16* Wh = g_wh + (size_t)w_idx * H_ * H_;
    const __nv_bfloat16* Wl = g_wl + (size_t)w_idx * H_ * H_;
    float* C = (c_sel == 0) ? g_q : (c_sel == 1) ? g_k : (c_sel == 2) ? g_v : extC;

    // loader mapping: idx -> (row r, 16B-group cc)
    const int r0i = t >> 2, c0i = t & 3;           // idx = t
    const int r1i = (t + 256) >> 2, c1i = t & 3;   // idx = t+256

    float acc[4][4][4];
#pragma unroll
    for (int i = 0; i < 4; i++)
#pragma unroll
        for (int j = 0; j < 4; j++) {
            acc[i][j][0] = 0.f; acc[i][j][1] = 0.f; acc[i][j][2] = 0.f; acc[i][j][3] = 0.f;
        }

    // ---- issue chunk `ci` into stage `s`
    auto issue = [&](int ci, int s) {
        int kc = ci * KC;
        uint32_t stb = sb + s * STAGEB;
        {
            size_t ga = (size_t)(bm + r0i) * H_ + kc + c0i * 8;
            size_t gb = (size_t)(bn + r0i) * H_ + kc + c0i * 8;
            uint32_t so = (uint32_t)(r0i * RS + c0i * 8) * 2;
            CP16(stb + 0 * TILEB + so, g_ah + ga);
            CP16(stb + 1 * TILEB + so, g_al + ga);
            CP16(stb + 2 * TILEB + so, Wh + gb);
            CP16(stb + 3 * TILEB + so, Wl + gb);
        }
        {
            size_t ga = (size_t)(bm + r1i) * H_ + kc + c1i * 8;
            size_t gb = (size_t)(bn + r1i) * H_ + kc + c1i * 8;
            uint32_t so = (uint32_t)(r1i * RS + c1i * 8) * 2;
            CP16(stb + 0 * TILEB + so, g_ah + ga);
            CP16(stb + 1 * TILEB + so, g_al + ga);
            CP16(stb + 2 * TILEB + so, Wh + gb);
            CP16(stb + 3 * TILEB + so, Wl + gb);
        }
        asm volatile("cp.async.commit_group;" ::: "memory");
    };

    issue(0, 0);

    const int NCH = H_ / KC;   // 64
    for (int ci = 0; ci < NCH; ci++) {
        int s = ci & 1;
        if (ci + 1 < NCH) {
            issue(ci + 1, s ^ 1);
            asm volatile("cp.async.wait_group 1;" ::: "memory");
        } else {
            asm volatile("cp.async.wait_group 0;" ::: "memory");
        }
        __syncthreads();

        const char* st = smem + s * STAGEB;
        const char* pAh = st;
        const char* pAl = st + TILEB;
        const char* pBh = st + 2 * TILEB;
        const char* pBl = st + 3 * TILEB;

#pragma unroll
        for (int ks = 0; ks < 2; ks++) {
            const int kb = ks * 16;
            uint32_t ah[4][4], al[4][4], bh[4][2], bl[4][2];
#pragma unroll
            for (int mt = 0; mt < 4; mt++) {
                int am = wm * 64 + mt * 16;
                uint32_t o0 = (uint32_t)((am + g)     * RS + kb + tig2) * 2;
                uint32_t o1 = (uint32_t)((am + g + 8) * RS + kb + tig2) * 2;
                ah[mt][0] = *(const uint32_t*)(pAh + o0);
                ah[mt][1] = *(const uint32_t*)(pAh + o1);
                ah[mt][2] = *(const uint32_t*)(pAh + o0 + 16);
                ah[mt][3] = *(const uint32_t*)(pAh + o1 + 16);
                al[mt][0] = *(const uint32_t*)(pAl + o0);
                al[mt][1] = *(const uint32_t*)(pAl + o1);
                al[mt][2] = *(const uint32_t*)(pAl + o0 + 16);
                al[mt][3] = *(const uint32_t*)(pAl + o1 + 16);
            }
#pragma unroll
            for (int nt = 0; nt < 4; nt++) {
                int an = wn * 32 + nt * 8;
                uint32_t o = (uint32_t)((an + g) * RS + kb + tig2) * 2;
                bh[nt][0] = *(const uint32_t*)(pBh + o);
                bh[nt][1] = *(const uint32_t*)(pBh + o + 16);
                bl[nt][0] = *(const uint32_t*)(pBl + o);
                bl[nt][1] = *(const uint32_t*)(pBl + o + 16);
            }
#pragma unroll
            for (int mt = 0; mt < 4; mt++)
#pragma unroll
                for (int nt = 0; nt < 4; nt++) {
                    float* c = acc[mt][nt];
                    mma_bf16(c[0], c[1], c[2], c[3],
                             ah[mt][0], ah[mt][1], ah[mt][2], ah[mt][3],
                             bh[nt][0], bh[nt][1]);
                    mma_bf16(c[0], c[1], c[2], c[3],
                             ah[mt][0], ah[mt][1], ah[mt][2], ah[mt][3],
                             bl[nt][0], bl[nt][1]);
                    mma_bf16(c[0], c[1], c[2], c[3],
                             al[mt][0], al[mt][1], al[mt][2], al[mt][3],
                             bh[nt][0], bh[nt][1]);
                }
        }
        __syncthreads();
    }

    // ---- epilogue: direct float2 stores
#pragma unroll
    for (int mt = 0; mt < 4; mt++) {
#pragma unroll
        for (int nt = 0; nt < 4; nt++) {
            int row = bm + wm * 64 + mt * 16 + g;
            int col = bn + wn * 32 + nt * 8 + tig2;
            float* c = acc[mt][nt];
            *(float2*)&C[(size_t)row * H_ + col]       = make_float2(c[0], c[1]);
            *(float2*)&C[(size_t)(row + 8) * H_ + col] = make_float2(c[2], c[3]);
        }
    }
}

// ===================== RoPE (proven) =====================
__global__ void rope_naive(const int* __restrict__ pos_ids) {
    int row = blockIdx.x;
    int b = row / S_;
    int s = row - b * S_;
    int pos = pos_ids[b * S_ + s];
    for (int u = threadIdx.x; u < NH_ * 64; u += 256) {
        int hh = u >> 6, j = u & 63;
        float invf = (float)exp(-(double)(2 * j) * (1.0 / 128.0) * log(10000.0));
        float ang = (float)pos * invf;
        float c, sn;
        c = cosf(ang); sn = sinf(ang);
        size_t base = (size_t)row * H_ + hh * HD_;
        float q1 = g_q[base + j], q2 = g_q[base + j + 64];
        g_q[base + j]      = q1 * c - q2 * sn;
        g_q[base + j + 64] = q2 * c + q1 * sn;
        float k1 = g_k[base + j], k2 = g_k[base + j + 64];
        g_k[base + j]      = k1 * c - k2 * sn;
        g_k[base + j + 64] = k2 * c + k1 * sn;
    }
}

// ===================== Flash attention (proven in R7) =====================
#define ASM_FLOATS 29568

__global__ void attn_fast() {
    extern __shared__ float sm[];
    float* Qs = sm;
    float* Ks = sm + 8448;
    float* Vs = sm + 16704;
    float* Ps = sm + 25152;
    float* rm = sm + 29376;
    float* rl = sm + 29440;
    float* rc = sm + 29504;

    int qi = blockIdx.x, bh = blockIdx.y;
    int b = bh / NH_, hh = bh % NH_;
    int t = threadIdx.x, lane = t & 31, w = t >> 5;
    int r0 = w << 3;

    const float* Qg = g_q + (size_t)(b * S_) * H_ + hh * HD_;
    const float* Kg = g_k + (size_t)(b * S_) * H_ + hh * HD_;
    const float* Vg = g_v + (size_t)(b * S_) * H_ + hh * HD_;

    for (int i = t; i < 64 * 32; i += 256) {
        int r = i >> 5, d4 = (i & 31) << 2;
        *(float4*)&Qs[r * 132 + d4] = *(const float4*)(Qg + (size_t)(qi * 64 + r) * H_ + d4);
    }
    if (t < 64) { rm[t] = -1e30f; rl[t] = 0.f; }

    float acc[8][4];
#pragma unroll
    for (int i = 0; i < 8; i++) { acc[i][0] = acc[i][1] = acc[i][2] = acc[i][3] = 0.f; }

    const float scale = 0.08838834764831845f;

    for (int kt = 0; kt <= qi; kt++) {
        __syncthreads();
        for (int i = t; i < 64 * 32; i += 256) {
            int r = i >> 5, d4 = (i & 31) << 2;
            float4 kv = *(const float4*)(Kg + (size_t)(kt * 64 + r) * H_ + d4);
            Ks[r * 129 + d4 + 0] = kv.x;
            Ks[r * 129 + d4 + 1] = kv.y;
            Ks[r * 129 + d4 + 2] = kv.z;
            Ks[r * 129 + d4 + 3] = kv.w;
            *(float4*)&Vs[r * 132 + d4] = *(const float4*)(Vg + (size_t)(kt * 64 + r) * H_ + d4);
        }
        __syncthreads();

        float s0[8], s1[8];
#pragma unroll
        for (int i = 0; i < 8; i++) { s0[i] = 0.f; s1[i] = 0.f; }
        const float* Ka = &Ks[lane * 129];
        const float* Kb2 = &Ks[(lane + 32) * 129];
#pragma unroll 4
        for (int d4 = 0; d4 < 128; d4 += 4) {
            float ka0 = Ka[d4+0], ka1 = Ka[d4+1], ka2 = Ka[d4+2], ka3 = Ka[d4+3];
            float kb0 = Kb2[d4+0], kb1 = Kb2[d4+1], kb2 = Kb2[d4+2], kb3 = Kb2[d4+3];
#pragma unroll
            for (int i = 0; i < 8; i++) {
                float4 qv = *(const float4*)&Qs[(r0 + i) * 132 + d4];
                s0[i] += qv.x * ka0 + qv.y * ka1 + qv.z * ka2 + qv.w * ka3;
                s1[i] += qv.x * kb0 + qv.y * kb1 + qv.z * kb2 + qv.w * kb3;
            }
        }
#pragma unroll
        for (int i = 0; i < 8; i++) {
            Ps[(r0 + i) * 66 + lane]      = s0[i];
            Ps[(r0 + i) * 66 + lane + 32] = s1[i];
        }
        __syncthreads();

        if (t < 64) {
            int r = t, grow = qi * 64 + r, cb = kt * 64;
            float mold = rm[r];
            float tmax = mold;
#pragma unroll 8
            for (int c = 0; c < 64; c++) {
                float a = Ps[r * 66 + c] * scale;
                if (cb + c > grow) a -= 10000.0f;
                Ps[r * 66 + c] = a;
                tmax = fmaxf(tmax, a);
            }
            float corr = __expf(mold - tmax);
            float psum = 0.f;
#pragma unroll 8
            for (int c = 0; c < 64; c++) {
                float p = __expf(Ps[r * 66 + c] - tmax);
                Ps[r * 66 + c] = p;
                psum += p;
            }
            rl[r] = rl[r] * corr + psum;
            rm[r] = tmax;
            rc[r] = corr;
        }
        __syncthreads();

        int d4 = lane << 2;
#pragma unroll
        for (int i = 0; i < 8; i++) {
            float corr = rc[r0 + i];
            acc[i][0] *= corr; acc[i][1] *= corr; acc[i][2] *= corr; acc[i][3] *= corr;
        }
#pragma unroll 2
        for (int c = 0; c < 64; c++) {
            float4 vv = *(const float4*)&Vs[c * 132 + d4];
#pragma unroll
            for (int i = 0; i < 8; i++) {
                float p = Ps[(r0 + i) * 66 + c];
                acc[i][0] += p * vv.x; acc[i][1] += p * vv.y;
                acc[i][2] += p * vv.z; acc[i][3] += p * vv.w;
            }
        }
    }

    int d4 = lane << 2;
#pragma unroll
    for (int i = 0; i < 8; i++) {
        float invl = 1.0f / rl[r0 + i];
        float* op = g_ctx + (size_t)(b * S_ + qi * 64 + r0 + i) * H_ + hh * HD_ + d4;
        *(float4*)op = make_float4(acc[i][0] * invl, acc[i][1] * invl,
                                   acc[i][2] * invl, acc[i][3] * invl);
    }
}

// ===================== launch =====================
extern "C" void kernel_launch(void* const* d_in, const int* in_sizes, int n_in,
                              void* d_out, int out_size) {
    (void)out_size;
    const float* x  = nullptr;
    const float* nw = nullptr;
    const int*  pos = nullptr;
    const float* wts[4] = {nullptr, nullptr, nullptr, nullptr};
    int wn = 0;
    for (int i = 0; i < n_in; i++) {
        int sz = in_sizes[i];
        if (sz == B_ * S_ * H_)      x = (const float*)d_in[i];
        else if (sz == H_)           nw = (const float*)d_in[i];
        else if (sz == B_ * S_)      pos = (const int*)d_in[i];
        else if (sz == H_ * H_ && wn < 4) wts[wn++] = (const float*)d_in[i];
    }
    float* out = (float*)d_out;

    rmsnorm_naive<<<M_, 256>>>(x, nw);

    const int wgrid = (H_ * H_) / (4 * 256);
    for (int i = 0; i < 4; i++)
        conv_split<<<wgrid, 256>>>(2, wts[i], 1, (size_t)i * H_ * H_);
    const int agrid = (M_ * H_) / (4 * 256);
    conv_split<<<agrid, 256>>>(0, nullptr, 0, 0);

    cudaFuncSetAttribute(gemm_mma, cudaFuncAttributeMaxDynamicSharedMemorySize, GSM_TOTAL);
    dim3 gg(H_ / 128, M_ / 128);
    gemm_mma<<<gg, 256, GSM_TOTAL>>>(0, 0, nullptr);   // Q
    gemm_mma<<<gg, 256, GSM_TOTAL>>>(1, 1, nullptr);   // K
    gemm_mma<<<gg, 256, GSM_TOTAL>>>(2, 2, nullptr);   // V

    rope_naive<<<M_, 256>>>(pos);

    cudaFuncSetAttribute(attn_fast, cudaFuncAttributeMaxDynamicSharedMemorySize,
                         ASM_FLOATS * 4);
    attn_fast<<<dim3(S_ / 64, B_ * NH_), 256, ASM_FLOATS * 4>>>();

    conv_split<<<agrid, 256>>>(1, nullptr, 0, 0);      // ctx split
    gemm_mma<<<gg, 256, GSM_TOTAL>>>(3, 3, out);       // O
}